// round 13
// baseline (speedup 1.0000x reference)
#include <cuda_runtime.h>
#include <math.h>

#define B_   4
#define S_   2048
#define H_   12
#define DM   768
#define DL   128
#define DQK  128
#define DV   128
#define MTOK (B_*S_)   // 8192

// ---------------- scratch ----------------------------------------------------
__device__ float g_Ckv  [MTOK*DL];
__device__ float g_Cq   [MTOK*DL];
__device__ float g_qnope[MTOK*H_*64];
__device__ float g_qrope[MTOK*H_*64];
__device__ float g_knope[MTOK*H_*64];
__device__ float g_krope[MTOK*H_*64];
__device__ float g_v    [MTOK*H_*DV];   // (b,s,h,dv) tf32, dv-permuted (vpos)
__device__ float g_q    [B_*H_*S_*DQK]; // (b*h,s,d) tf32*scale, kpos-permuted
__device__ float g_k    [B_*H_*S_*DQK]; // (b*h,s,d) tf32, kpos-permuted
__device__ float g_o    [MTOK*H_*DV];   // (b,s,h,dv)

// ---------------- tf32 / cp.async helpers ------------------------------------
__device__ __forceinline__ unsigned f2tf(float x) {
    unsigned r; asm("cvt.rna.tf32.f32 %0, %1;" : "=r"(r) : "f"(x)); return r;
}
__device__ __forceinline__ float f2tff(float x) {
    return __uint_as_float(f2tf(x));
}
__device__ __forceinline__ void mma8(float* d, const unsigned* a,
                                     const unsigned* b) {
    asm volatile(
        "mma.sync.aligned.m16n8k8.row.col.f32.tf32.tf32.f32 "
        "{%0,%1,%2,%3}, {%4,%5,%6,%7}, {%8,%9}, {%0,%1,%2,%3};"
        : "+f"(d[0]), "+f"(d[1]), "+f"(d[2]), "+f"(d[3])
        : "r"(a[0]), "r"(a[1]), "r"(a[2]), "r"(a[3]), "r"(b[0]), "r"(b[1]));
}
__device__ __forceinline__ void cpa16(unsigned dst, const float* src) {
    asm volatile("cp.async.ca.shared.global [%0], [%1], 16;"
                 :: "r"(dst), "l"(src));
}
__device__ __forceinline__ void cpa_commit() {
    asm volatile("cp.async.commit_group;");
}
__device__ __forceinline__ void cpa_wait0() {
    asm volatile("cp.async.wait_group 0;");
}
// storage permutations (pure layout; values land in identical mma slots)
__device__ __forceinline__ int kpos(int d) {          // Q/K: within 16-block
    int o = d & 15; return (d & ~15) + ((o & 3) << 2) + (o >> 2);
}
__device__ __forceinline__ int vpos(int c) {          // V: within 32-block
    int r = c & 31; return (c & ~31) + ((r & 7) << 2) + (r >> 3);
}

// ---------------- tf32 GEMM (dual-job, z-select — profiled fastest) ----------
struct GemmJob {
    const float* A; const float* W; const float* bias; float* C;
    int N; int K; int permv;   // permv: tf32-round + dv-permute stores (V)
};

#define GSTR 20
__global__ __launch_bounds__(256) void gemm_tf32_dual(GemmJob j0, GemmJob j1) {
    const GemmJob j = blockIdx.z ? j1 : j0;
    const int N = j.N, K = j.K;
    const int n0 = blockIdx.x << 7;
    if (n0 >= N) return;
    const float* __restrict__ A = j.A;
    const float* __restrict__ W = j.W;
    __shared__ float As[128 * GSTR];
    __shared__ float Ws[128 * GSTR];
    const int tid = threadIdx.x, lane = tid & 31, wid = tid >> 5;
    const int m0 = blockIdx.y << 7;
    const int wm = wid & 1, wn = wid >> 1;
    const int g  = lane >> 2, t4 = lane & 3;
    float acc[4][4][4];
    #pragma unroll
    for (int i = 0; i < 4; ++i)
        #pragma unroll
        for (int jj = 0; jj < 4; ++jj)
            #pragma unroll
            for (int e = 0; e < 4; ++e) acc[i][jj][e] = 0.f;

    const int lrow0 = tid >> 2, lcol = (tid & 3) << 2;
    float4 ar[2], wr_[2];
    {
        ar[0]  = *(const float4*)(A + (size_t)(m0 + lrow0) * K + lcol);
        ar[1]  = *(const float4*)(A + (size_t)(m0 + lrow0 + 64) * K + lcol);
        wr_[0] = *(const float4*)(W + (size_t)(n0 + lrow0) * K + lcol);
        wr_[1] = *(const float4*)(W + (size_t)(n0 + lrow0 + 64) * K + lcol);
    }
    for (int k0 = 0; k0 < K; k0 += 16) {
        __syncthreads();
        #pragma unroll
        for (int jj = 0; jj < 2; ++jj) {
            int row = lrow0 + jj * 64;
            float* pa = As + row * GSTR + lcol;
            pa[0] = f2tff(ar[jj].x); pa[1] = f2tff(ar[jj].y);
            pa[2] = f2tff(ar[jj].z); pa[3] = f2tff(ar[jj].w);
            float* pw = Ws + row * GSTR + lcol;
            pw[0] = f2tff(wr_[jj].x); pw[1] = f2tff(wr_[jj].y);
            pw[2] = f2tff(wr_[jj].z); pw[3] = f2tff(wr_[jj].w);
        }
        __syncthreads();
        if (k0 + 16 < K) {
            int kc = k0 + 16 + lcol;
            ar[0]  = *(const float4*)(A + (size_t)(m0 + lrow0) * K + kc);
            ar[1]  = *(const float4*)(A + (size_t)(m0 + lrow0 + 64) * K + kc);
            wr_[0] = *(const float4*)(W + (size_t)(n0 + lrow0) * K + kc);
            wr_[1] = *(const float4*)(W + (size_t)(n0 + lrow0 + 64) * K + kc);
        }
        #pragma unroll
        for (int ks = 0; ks < 2; ++ks) {
            unsigned af[4][4], bf[4][2];
            #pragma unroll
            for (int mf = 0; mf < 4; ++mf) {
                int row = wm * 64 + mf * 16 + g;
                int col = ks * 8 + t4;
                af[mf][0] = __float_as_uint(As[row * GSTR + col]);
                af[mf][1] = __float_as_uint(As[(row + 8) * GSTR + col]);
                af[mf][2] = __float_as_uint(As[row * GSTR + col + 4]);
                af[mf][3] = __float_as_uint(As[(row + 8) * GSTR + col + 4]);
            }
            #pragma unroll
            for (int nf = 0; nf < 4; ++nf) {
                int n = wn * 32 + nf * 8 + g;
                int kk = ks * 8 + t4;
                bf[nf][0] = __float_as_uint(Ws[n * GSTR + kk]);
                bf[nf][1] = __float_as_uint(Ws[n * GSTR + kk + 4]);
            }
            #pragma unroll
            for (int mf = 0; mf < 4; ++mf)
                #pragma unroll
                for (int nf = 0; nf < 4; ++nf)
                    mma8(acc[mf][nf], af[mf], bf[nf]);
        }
    }
    if (j.permv) {
        #pragma unroll
        for (int mf = 0; mf < 4; ++mf) {
            int row = m0 + wm * 64 + mf * 16 + g;
            #pragma unroll
            for (int nf = 0; nf < 4; ++nf) {
                int col = n0 + wn * 32 + nf * 8 + 2 * t4;
                float b0 = j.bias[col], b1 = j.bias[col + 1];
                int p0 = (col & ~127) | vpos(col & 127);
                int p1 = ((col + 1) & ~127) | vpos((col + 1) & 127);
                j.C[(size_t)row * N + p0]       = f2tff(acc[mf][nf][0] + b0);
                j.C[(size_t)row * N + p1]       = f2tff(acc[mf][nf][1] + b1);
                j.C[(size_t)(row + 8) * N + p0] = f2tff(acc[mf][nf][2] + b0);
                j.C[(size_t)(row + 8) * N + p1] = f2tff(acc[mf][nf][3] + b1);
            }
        }
    } else {
        #pragma unroll
        for (int mf = 0; mf < 4; ++mf) {
            int row = m0 + wm * 64 + mf * 16 + g;
            #pragma unroll
            for (int nf = 0; nf < 4; ++nf) {
                int col = n0 + wn * 32 + nf * 8 + 2 * t4;
                float b0 = j.bias[col], b1 = j.bias[col + 1];
                j.C[(size_t)row * N + col]           = acc[mf][nf][0] + b0;
                j.C[(size_t)row * N + col + 1]       = acc[mf][nf][1] + b1;
                j.C[(size_t)(row + 8) * N + col]     = acc[mf][nf][2] + b0;
                j.C[(size_t)(row + 8) * N + col + 1] = acc[mf][nf][3] + b1;
            }
        }
    }
}

// ---------------- RoPE + head repack (Q AND K stored kpos-permuted) ----------
__global__ void pack_qk(const int* __restrict__ pos) {
    int idx = blockIdx.x * blockDim.x + threadIdx.x;
    if (idx >= MTOK * 384) return;
    int p = idx % 384;
    int m = idx / 384;
    int s = m & (S_ - 1);
    int b = m >> 11;
    size_t nb = (size_t)m * 768;
    const float scale = 0.0883883476483184f;   // 1/sqrt(128)
    {   // nope pair -> heads 0-5
        int c = 2 * p;
        int h = c >> 7, d = c & 127;
        size_t rowb = ((size_t)(b * H_ + h) * S_ + s) * DQK;
        g_q[rowb + kpos(d)]   = f2tff(g_qnope[nb + c] * scale);
        g_q[rowb + kpos(d+1)] = f2tff(g_qnope[nb + c + 1] * scale);
        g_k[rowb + kpos(d)]   = f2tff(g_knope[nb + c]);
        g_k[rowb + kpos(d+1)] = f2tff(g_knope[nb + c + 1]);
    }
    {   // rope pair -> heads 6-11, freq over full 768-dim vector
        float inv_freq = powf(10000.0f, -(float)(2 * p) / 768.0f);
        float ang = (float)pos[s] * inv_freq;
        float sn, cs;
        sincosf(ang, &sn, &cs);
        int e = 2 * p;
        int h = 6 + (e >> 7), d = e & 127;
        size_t rowb = ((size_t)(b * H_ + h) * S_ + s) * DQK;
        float qe = g_qrope[nb + e], qo = g_qrope[nb + e + 1];
        g_q[rowb + kpos(d)]   = f2tff((qe * cs - qo * sn) * scale);
        g_q[rowb + kpos(d+1)] = f2tff((qe * sn + qo * cs) * scale);
        float ke = g_krope[nb + e], ko = g_krope[nb + e + 1];
        g_k[rowb + kpos(d)]   = f2tff(ke * cs - ko * sn);
        g_k[rowb + kpos(d+1)] = f2tff(ke * sn + ko * cs);
    }
}

// ---------------- flash attention v5: smem Q, all-vector fragment loads ------
// q-tile 128, 8 warps x 16 rows. Q in smem (kpos-permuted): 2 LDS.128 per k2
// feed both mma a-frags. K: 1 LDS.128 per (k2,nf) feeds 2 mma. V dv-permuted:
// 1 LDS.128 feeds 4 nf. cp.async double-buffered K/V, one barrier per tile.
#define QSTR 132
#define KSTR 132
#define ATT_SMEM ((128*QSTR + 4*64*KSTR) * 4)   // 202752 bytes

__global__ __launch_bounds__(256, 1) void attn_mma() {
    extern __shared__ float sm[];
    const unsigned smb = (unsigned)__cvta_generic_to_shared(sm);
    const unsigned kvb = smb + 128 * QSTR * 4;
    const int qt = gridDim.x - 1 - blockIdx.x;
    const int bh = blockIdx.y;
    const int b = bh / H_, h = bh % H_;
    const int tid = threadIdx.x, lane = tid & 31, wid = tid >> 5;
    const int g = lane >> 2, t4 = lane & 3;

    const float* qg = g_q + ((size_t)bh * S_ + qt * 128) * DQK;
    const float* kg = g_k + (size_t)bh * S_ * DQK;
    const float* vg = g_v + (size_t)(b * S_) * (H_ * DV) + h * DV;
    const int nt = 2 * qt + 2;

    // prologue: Q (16 chunks/thread) + K/V tile 0, one group
    #pragma unroll
    for (int jj = 0; jj < 16; ++jj) {
        int idx = tid + jj * 256;
        int rr = idx >> 5, c4 = (idx & 31) << 2;
        cpa16(smb + (rr * QSTR + c4) * 4, qg + (size_t)rr * DQK + c4);
    }
    #pragma unroll
    for (int jj = 0; jj < 8; ++jj) {
        int idx = tid + jj * 256;
        int rr = idx >> 5, c4 = (idx & 31) << 2;
        cpa16(kvb + (rr * KSTR + c4) * 4, kg + (size_t)rr * DQK + c4);
        cpa16(kvb + ((2 * 64 + rr) * KSTR + c4) * 4,
              vg + (size_t)rr * (H_ * DV) + c4);
    }
    cpa_commit();

    const int r0l  = wid * 16 + g;
    const int r0gl = qt * 128 + r0l;

    float oc[16][4];
    #pragma unroll
    for (int i = 0; i < 16; ++i)
        #pragma unroll
        for (int e = 0; e < 4; ++e) oc[i][e] = 0.f;

    float m0 = -1e30f, m1 = -1e30f, l0 = 0.f, l1 = 0.f;

    for (int t = 0; t < nt; ++t) {
        cpa_wait0();
        __syncthreads();
        if (t + 1 < nt) {
            int bsel = (t + 1) & 1;
            const float* kgn = kg + (size_t)(t + 1) * 64 * DQK;
            const float* vgn = vg + (size_t)(t + 1) * 64 * (H_ * DV);
            #pragma unroll
            for (int jj = 0; jj < 8; ++jj) {
                int idx = tid + jj * 256;
                int rr = idx >> 5, c4 = (idx & 31) << 2;
                cpa16(kvb + ((bsel * 64 + rr) * KSTR + c4) * 4,
                      kgn + (size_t)rr * DQK + c4);
                cpa16(kvb + (((2 + bsel) * 64 + rr) * KSTR + c4) * 4,
                      vgn + (size_t)rr * (H_ * DV) + c4);
            }
            cpa_commit();
        }
        const float* Kd = sm + 128 * QSTR + (t & 1) * 64 * KSTR;
        const float* Vd = sm + 128 * QSTR + (2 + (t & 1)) * 64 * KSTR;

        // ---- S = Q K^T : all fragments via LDS.128 -----------------------
        float sc[8][4];
        #pragma unroll
        for (int i = 0; i < 8; ++i)
            #pragma unroll
            for (int e = 0; e < 4; ++e) sc[i][e] = 0.f;
        const float* qrow = sm + r0l * QSTR + 4 * t4;
        #pragma unroll
        for (int k2 = 0; k2 < 8; ++k2) {
            float4 qlo = *(const float4*)(qrow + 16 * k2);
            float4 qhi = *(const float4*)(qrow + 8 * QSTR + 16 * k2);
            unsigned alo[4] = {__float_as_uint(qlo.x), __float_as_uint(qhi.x),
                               __float_as_uint(qlo.y), __float_as_uint(qhi.y)};
            unsigned ahi[4] = {__float_as_uint(qlo.z), __float_as_uint(qhi.z),
                               __float_as_uint(qlo.w), __float_as_uint(qhi.w)};
            #pragma unroll
            for (int nf = 0; nf < 8; ++nf) {
                float4 kv = *(const float4*)(Kd + (nf * 8 + g) * KSTR
                                             + 16 * k2 + 4 * t4);
                unsigned blo[2] = {__float_as_uint(kv.x), __float_as_uint(kv.y)};
                unsigned bhi[2] = {__float_as_uint(kv.z), __float_as_uint(kv.w)};
                mma8(sc[nf], alo, blo);
                mma8(sc[nf], ahi, bhi);
            }
        }
        // ---- causal mask -------------------------------------------------
        if (t >= 2 * qt) {
            #pragma unroll
            for (int nf = 0; nf < 8; ++nf) {
                int k0 = t * 64 + nf * 8 + 2 * t4;
                if (k0     > r0gl)     sc[nf][0] = -1e30f;
                if (k0 + 1 > r0gl)     sc[nf][1] = -1e30f;
                if (k0     > r0gl + 8) sc[nf][2] = -1e30f;
                if (k0 + 1 > r0gl + 8) sc[nf][3] = -1e30f;
            }
        }
        // ---- online softmax on register fragments ------------------------
        float ml0 = -1e30f, ml1 = -1e30f;
        #pragma unroll
        for (int nf = 0; nf < 8; ++nf) {
            ml0 = fmaxf(ml0, fmaxf(sc[nf][0], sc[nf][1]));
            ml1 = fmaxf(ml1, fmaxf(sc[nf][2], sc[nf][3]));
        }
        ml0 = fmaxf(ml0, __shfl_xor_sync(0xffffffffu, ml0, 1));
        ml0 = fmaxf(ml0, __shfl_xor_sync(0xffffffffu, ml0, 2));
        ml1 = fmaxf(ml1, __shfl_xor_sync(0xffffffffu, ml1, 1));
        ml1 = fmaxf(ml1, __shfl_xor_sync(0xffffffffu, ml1, 2));
        float mn0 = fmaxf(m0, ml0), mn1 = fmaxf(m1, ml1);
        float a0 = __expf(m0 - mn0), a1 = __expf(m1 - mn1);
        float s0 = 0.f, s1 = 0.f;
        #pragma unroll
        for (int nf = 0; nf < 8; ++nf) {
            float p00 = __expf(sc[nf][0] - mn0);
            float p01 = __expf(sc[nf][1] - mn0);
            float p10 = __expf(sc[nf][2] - mn1);
            float p11 = __expf(sc[nf][3] - mn1);
            s0 += p00 + p01; s1 += p10 + p11;
            sc[nf][0] = f2tff(p00); sc[nf][1] = f2tff(p01);
            sc[nf][2] = f2tff(p10); sc[nf][3] = f2tff(p11);
        }
        s0 += __shfl_xor_sync(0xffffffffu, s0, 1);
        s0 += __shfl_xor_sync(0xffffffffu, s0, 2);
        s1 += __shfl_xor_sync(0xffffffffu, s1, 1);
        s1 += __shfl_xor_sync(0xffffffffu, s1, 2);
        l0 = l0 * a0 + s0; l1 = l1 * a1 + s1;
        m0 = mn0; m1 = mn1;
        #pragma unroll
        for (int nf = 0; nf < 16; ++nf) {
            oc[nf][0] *= a0; oc[nf][1] *= a0;
            oc[nf][2] *= a1; oc[nf][3] *= a1;
        }
        // ---- O += P V : shfl P to A-frag; LDS.128 feeds 4 nf -------------
        const int srcA = (lane & ~3) | (t4 >> 1);
        const bool odd = (t4 & 1);
        #pragma unroll
        for (int ks = 0; ks < 8; ++ks) {
            float e0A = __shfl_sync(0xffffffffu, sc[ks][0], srcA);
            float e1A = __shfl_sync(0xffffffffu, sc[ks][1], srcA);
            float e2A = __shfl_sync(0xffffffffu, sc[ks][2], srcA);
            float e3A = __shfl_sync(0xffffffffu, sc[ks][3], srcA);
            float e0B = __shfl_sync(0xffffffffu, sc[ks][0], srcA + 2);
            float e1B = __shfl_sync(0xffffffffu, sc[ks][1], srcA + 2);
            float e2B = __shfl_sync(0xffffffffu, sc[ks][2], srcA + 2);
            float e3B = __shfl_sync(0xffffffffu, sc[ks][3], srcA + 2);
            unsigned pa[4];
            pa[0] = __float_as_uint(odd ? e1A : e0A);
            pa[1] = __float_as_uint(odd ? e3A : e2A);
            pa[2] = __float_as_uint(odd ? e1B : e0B);
            pa[3] = __float_as_uint(odd ? e3B : e2B);
            const float* vr0 = Vd + (ks * 8 + t4) * KSTR + 4 * g;
            const float* vr4 = vr0 + 4 * KSTR;
            #pragma unroll
            for (int q = 0; q < 4; ++q) {
                float4 vlo = *(const float4*)(vr0 + q * 32);
                float4 vhi = *(const float4*)(vr4 + q * 32);
                unsigned vb0[2] = {__float_as_uint(vlo.x), __float_as_uint(vhi.x)};
                unsigned vb1[2] = {__float_as_uint(vlo.y), __float_as_uint(vhi.y)};
                unsigned vb2_[2] = {__float_as_uint(vlo.z), __float_as_uint(vhi.z)};
                unsigned vb3[2] = {__float_as_uint(vlo.w), __float_as_uint(vhi.w)};
                mma8(oc[4 * q],     pa, vb0);
                mma8(oc[4 * q + 1], pa, vb1);
                mma8(oc[4 * q + 2], pa, vb2_);
                mma8(oc[4 * q + 3], pa, vb3);
            }
        }
    }
    // ---- epilogue (oc[nf] covers ORIGINAL dv cols 8nf+g — perm cancels) --
    float il0 = 1.0f / l0, il1 = 1.0f / l1;
    float* ob = g_o + ((size_t)(b * S_) + r0gl) * (H_ * DV) + h * DV;
    float* ob1 = ob + 8 * (size_t)(H_ * DV);
    #pragma unroll
    for (int nf = 0; nf < 16; ++nf) {
        int col = nf * 8 + 2 * t4;
        *(float2*)(ob  + col) = make_float2(oc[nf][0] * il0, oc[nf][1] * il0);
        *(float2*)(ob1 + col) = make_float2(oc[nf][2] * il1, oc[nf][3] * il1);
    }
}

// ---------------- launcher ---------------------------------------------------
extern "C" void kernel_launch(void* const* d_in, const int* in_sizes, int n_in,
                              void* d_out, int out_size) {
    const float* x         = (const float*)d_in[0];
    const int*   pos       = (const int*)  d_in[1];
    const float* W_dkv     = (const float*)d_in[2];
    const float* b_dkv     = (const float*)d_in[3];
    const float* W_dq      = (const float*)d_in[4];
    const float* b_dq      = (const float*)d_in[5];
    const float* W_uk_nope = (const float*)d_in[6];
    const float* b_uk_nope = (const float*)d_in[7];
    const float* W_uv      = (const float*)d_in[8];
    const float* b_uv      = (const float*)d_in[9];
    const float* W_uq_nope = (const float*)d_in[10];
    const float* b_uq_nope = (const float*)d_in[11];
    const float* W_uq_rope = (const float*)d_in[12];
    const float* b_uq_rope = (const float*)d_in[13];
    const float* W_uk_rope = (const float*)d_in[14];
    const float* b_uk_rope = (const float*)d_in[15];
    const float* W_o       = (const float*)d_in[16];
    const float* b_o       = (const float*)d_in[17];
    float* out = (float*)d_out;

    float *Ckv, *Cq, *qn, *qr, *kn, *kr, *v, *o;
    cudaGetSymbolAddress((void**)&Ckv, g_Ckv);
    cudaGetSymbolAddress((void**)&Cq,  g_Cq);
    cudaGetSymbolAddress((void**)&qn,  g_qnope);
    cudaGetSymbolAddress((void**)&qr,  g_qrope);
    cudaGetSymbolAddress((void**)&kn,  g_knope);
    cudaGetSymbolAddress((void**)&kr,  g_krope);
    cudaGetSymbolAddress((void**)&v,   g_v);
    cudaGetSymbolAddress((void**)&o,   g_o);

    auto launch2 = [&](GemmJob a, GemmJob b) {
        int nmax = a.N > b.N ? a.N : b.N;
        dim3 grid(nmax / 128, MTOK / 128, 2);
        gemm_tf32_dual<<<grid, 256>>>(a, b);
    };
    auto launch1 = [&](GemmJob a) {
        dim3 grid(a.N / 128, MTOK / 128, 1);
        gemm_tf32_dual<<<grid, 256>>>(a, a);
    };

    // #1: dkv + dq (A = x)
    launch2({x, W_dkv, b_dkv, Ckv, DL, DM, 0}, {x, W_dq, b_dq, Cq, DL, DM, 0});
    // #2: uk_rope (A = x)
    launch1({x, W_uk_rope, b_uk_rope, kr, H_*64, DM, 0});
    // #3: uq_nope + uq_rope (A = Cq)
    launch2({Cq, W_uq_nope, b_uq_nope, qn, H_*64, DL, 0},
            {Cq, W_uq_rope, b_uq_rope, qr, H_*64, DL, 0});
    // #4: uk_nope + uv (A = Ckv); v tf32-rounded + dv-permuted at producer
    launch2({Ckv, W_uk_nope, b_uk_nope, kn, H_*64, DL, 0},
            {Ckv, W_uv, b_uv, v, H_*DV, DL, 1});
    // #5: pack/rope (q/k kpos-permuted tf32; q pre-scaled)
    int packTotal = MTOK * 384;
    pack_qk<<<(packTotal + 255) / 256, 256>>>(pos);
    // #6: attention
    cudaFuncSetAttribute(attn_mma, cudaFuncAttributeMaxDynamicSharedMemorySize,
                         ATT_SMEM);
    attn_mma<<<dim3(S_ / 128, B_ * H_), 256, ATT_SMEM>>>();
    // #7: output projection
    launch1({o, W_o, b_o, out, DM, H_*DV, 0});
}

// round 14
// speedup vs baseline: 1.3449x; 1.3449x over previous
#include <cuda_runtime.h>
#include <cuda_bf16.h>
#include <math.h>

#define B_   4
#define S_   2048
#define H_   12
#define DM   768
#define DL   128
#define DQK  128
#define DV   128
#define MTOK (B_*S_)   // 8192

// ---------------- scratch ----------------------------------------------------
__device__ float g_Ckv  [MTOK*DL];
__device__ float g_Cq   [MTOK*DL];
__device__ float g_qnope[MTOK*H_*64];
__device__ float g_qrope[MTOK*H_*64];
__device__ float g_knope[MTOK*H_*64];
__device__ float g_krope[MTOK*H_*64];
__device__ float g_v    [MTOK*H_*DV];           // (b,s,h,dv) tf32-rounded
__device__ __nv_bfloat16 g_qh[B_*H_*S_*DQK];    // (b*h,s,d) bf16, scale folded
__device__ __nv_bfloat16 g_kh[B_*H_*S_*DQK];    // (b*h,s,d) bf16
__device__ float g_o    [MTOK*H_*DV];           // (b,s,h,dv)

// ---------------- helpers ----------------------------------------------------
__device__ __forceinline__ unsigned f2tf(float x) {
    unsigned r; asm("cvt.rna.tf32.f32 %0, %1;" : "=r"(r) : "f"(x)); return r;
}
__device__ __forceinline__ float f2tff(float x) {
    return __uint_as_float(f2tf(x));
}
__device__ __forceinline__ void mma8(float* d, const unsigned* a,
                                     const unsigned* b) {
    asm volatile(
        "mma.sync.aligned.m16n8k8.row.col.f32.tf32.tf32.f32 "
        "{%0,%1,%2,%3}, {%4,%5,%6,%7}, {%8,%9}, {%0,%1,%2,%3};"
        : "+f"(d[0]), "+f"(d[1]), "+f"(d[2]), "+f"(d[3])
        : "r"(a[0]), "r"(a[1]), "r"(a[2]), "r"(a[3]), "r"(b[0]), "r"(b[1]));
}
__device__ __forceinline__ void mma16bf(float* d, const unsigned* a,
                                        const unsigned* b) {
    asm volatile(
        "mma.sync.aligned.m16n8k16.row.col.f32.bf16.bf16.f32 "
        "{%0,%1,%2,%3}, {%4,%5,%6,%7}, {%8,%9}, {%0,%1,%2,%3};"
        : "+f"(d[0]), "+f"(d[1]), "+f"(d[2]), "+f"(d[3])
        : "r"(a[0]), "r"(a[1]), "r"(a[2]), "r"(a[3]), "r"(b[0]), "r"(b[1]));
}
__device__ __forceinline__ void cpa16(unsigned dst, const void* src) {
    asm volatile("cp.async.ca.shared.global [%0], [%1], 16;"
                 :: "r"(dst), "l"(src));
}
__device__ __forceinline__ void cpa_commit() {
    asm volatile("cp.async.commit_group;");
}
__device__ __forceinline__ void cpa_wait0() {
    asm volatile("cp.async.wait_group 0;");
}

// ---------------- tf32 GEMM (dual-job, z-select — R9-proven) -----------------
struct GemmJob {
    const float* A; const float* W; const float* bias; float* C;
    int N; int K; int cvt;     // cvt: tf32-round outputs (V)
};

#define GSTR 20
__global__ __launch_bounds__(256) void gemm_tf32_dual(GemmJob j0, GemmJob j1) {
    const GemmJob j = blockIdx.z ? j1 : j0;
    const int N = j.N, K = j.K;
    const int n0 = blockIdx.x << 7;
    if (n0 >= N) return;
    const float* __restrict__ A = j.A;
    const float* __restrict__ W = j.W;
    __shared__ float As[128 * GSTR];
    __shared__ float Ws[128 * GSTR];
    const int tid = threadIdx.x, lane = tid & 31, wid = tid >> 5;
    const int m0 = blockIdx.y << 7;
    const int wm = wid & 1, wn = wid >> 1;
    const int g  = lane >> 2, t4 = lane & 3;
    float acc[4][4][4];
    #pragma unroll
    for (int i = 0; i < 4; ++i)
        #pragma unroll
        for (int jj = 0; jj < 4; ++jj)
            #pragma unroll
            for (int e = 0; e < 4; ++e) acc[i][jj][e] = 0.f;

    const int lrow0 = tid >> 2, lcol = (tid & 3) << 2;
    float4 ar[2], wr_[2];
    {
        ar[0]  = *(const float4*)(A + (size_t)(m0 + lrow0) * K + lcol);
        ar[1]  = *(const float4*)(A + (size_t)(m0 + lrow0 + 64) * K + lcol);
        wr_[0] = *(const float4*)(W + (size_t)(n0 + lrow0) * K + lcol);
        wr_[1] = *(const float4*)(W + (size_t)(n0 + lrow0 + 64) * K + lcol);
    }
    for (int k0 = 0; k0 < K; k0 += 16) {
        __syncthreads();
        #pragma unroll
        for (int jj = 0; jj < 2; ++jj) {
            int row = lrow0 + jj * 64;
            float* pa = As + row * GSTR + lcol;
            pa[0] = f2tff(ar[jj].x); pa[1] = f2tff(ar[jj].y);
            pa[2] = f2tff(ar[jj].z); pa[3] = f2tff(ar[jj].w);
            float* pw = Ws + row * GSTR + lcol;
            pw[0] = f2tff(wr_[jj].x); pw[1] = f2tff(wr_[jj].y);
            pw[2] = f2tff(wr_[jj].z); pw[3] = f2tff(wr_[jj].w);
        }
        __syncthreads();
        if (k0 + 16 < K) {
            int kc = k0 + 16 + lcol;
            ar[0]  = *(const float4*)(A + (size_t)(m0 + lrow0) * K + kc);
            ar[1]  = *(const float4*)(A + (size_t)(m0 + lrow0 + 64) * K + kc);
            wr_[0] = *(const float4*)(W + (size_t)(n0 + lrow0) * K + kc);
            wr_[1] = *(const float4*)(W + (size_t)(n0 + lrow0 + 64) * K + kc);
        }
        #pragma unroll
        for (int ks = 0; ks < 2; ++ks) {
            unsigned af[4][4], bf[4][2];
            #pragma unroll
            for (int mf = 0; mf < 4; ++mf) {
                int row = wm * 64 + mf * 16 + g;
                int col = ks * 8 + t4;
                af[mf][0] = __float_as_uint(As[row * GSTR + col]);
                af[mf][1] = __float_as_uint(As[(row + 8) * GSTR + col]);
                af[mf][2] = __float_as_uint(As[row * GSTR + col + 4]);
                af[mf][3] = __float_as_uint(As[(row + 8) * GSTR + col + 4]);
            }
            #pragma unroll
            for (int nf = 0; nf < 4; ++nf) {
                int n = wn * 32 + nf * 8 + g;
                int kk = ks * 8 + t4;
                bf[nf][0] = __float_as_uint(Ws[n * GSTR + kk]);
                bf[nf][1] = __float_as_uint(Ws[n * GSTR + kk + 4]);
            }
            #pragma unroll
            for (int mf = 0; mf < 4; ++mf)
                #pragma unroll
                for (int nf = 0; nf < 4; ++nf)
                    mma8(acc[mf][nf], af[mf], bf[nf]);
        }
    }
    const bool cvt = (j.cvt != 0);
    #pragma unroll
    for (int mf = 0; mf < 4; ++mf) {
        int row = m0 + wm * 64 + mf * 16 + g;
        #pragma unroll
        for (int nf = 0; nf < 4; ++nf) {
            int col = n0 + wn * 32 + nf * 8 + 2 * t4;
            float b0 = j.bias[col], b1 = j.bias[col + 1];
            float r00 = acc[mf][nf][0] + b0, r01 = acc[mf][nf][1] + b1;
            float r10 = acc[mf][nf][2] + b0, r11 = acc[mf][nf][3] + b1;
            if (cvt) { r00 = f2tff(r00); r01 = f2tff(r01);
                       r10 = f2tff(r10); r11 = f2tff(r11); }
            j.C[(size_t)row * N + col]           = r00;
            j.C[(size_t)row * N + col + 1]       = r01;
            j.C[(size_t)(row + 8) * N + col]     = r10;
            j.C[(size_t)(row + 8) * N + col + 1] = r11;
        }
    }
}

// ---------------- RoPE + head repack (Q/K -> bf16, natural order) ------------
__global__ void pack_qk(const int* __restrict__ pos) {
    int idx = blockIdx.x * blockDim.x + threadIdx.x;
    if (idx >= MTOK * 384) return;
    int p = idx % 384;
    int m = idx / 384;
    int s = m & (S_ - 1);
    int b = m >> 11;
    size_t nb = (size_t)m * 768;
    const float scale = 0.0883883476483184f;   // 1/sqrt(128)
    {   // nope pair -> heads 0-5
        int c = 2 * p;
        int h = c >> 7, d = c & 127;
        size_t rowb = ((size_t)(b * H_ + h) * S_ + s) * DQK;
        g_qh[rowb + d]     = __float2bfloat16(g_qnope[nb + c] * scale);
        g_qh[rowb + d + 1] = __float2bfloat16(g_qnope[nb + c + 1] * scale);
        g_kh[rowb + d]     = __float2bfloat16(g_knope[nb + c]);
        g_kh[rowb + d + 1] = __float2bfloat16(g_knope[nb + c + 1]);
    }
    {   // rope pair -> heads 6-11, freq over full 768-dim vector
        float inv_freq = powf(10000.0f, -(float)(2 * p) / 768.0f);
        float ang = (float)pos[s] * inv_freq;
        float sn, cs;
        sincosf(ang, &sn, &cs);
        int e = 2 * p;
        int h = 6 + (e >> 7), d = e & 127;
        size_t rowb = ((size_t)(b * H_ + h) * S_ + s) * DQK;
        float qe = g_qrope[nb + e], qo = g_qrope[nb + e + 1];
        g_qh[rowb + d]     = __float2bfloat16((qe * cs - qo * sn) * scale);
        g_qh[rowb + d + 1] = __float2bfloat16((qe * sn + qo * cs) * scale);
        float ke = g_krope[nb + e], ko = g_krope[nb + e + 1];
        g_kh[rowb + d]     = __float2bfloat16(ke * cs - ko * sn);
        g_kh[rowb + d + 1] = __float2bfloat16(ke * sn + ko * cs);
    }
}

// ---------------- flash attention v6: bf16 QK^T, tf32 PV (R9 base) -----------
// q-tile 128, 8 warps x 16 rows. Q/K bf16 in smem (b32 pair loads, same frag
// indexing as tf32 with half the k-steps). V fp32 as in R9. cp.async
// double-buffered K/V, one barrier per tile.
#define QSTRH 136            // bf16 halves per Q/K row (68 b32)
#define VSTR  132
#define SM_Q  0                              // 128*136*2 = 34816 B
#define SM_K  34816                          // 2 tiles * 64*136*2 = 34816 B
#define SM_V  69632                          // 2 tiles * 64*132*4 = 67584 B
#define ATT_SMEM 137216

__global__ __launch_bounds__(256, 1) void attn_mma() {
    extern __shared__ char smc[];
    const unsigned smb = (unsigned)__cvta_generic_to_shared(smc);
    const int qt = gridDim.x - 1 - blockIdx.x;   // big causal tiles first
    const int bh = blockIdx.y;
    const int b = bh / H_, h = bh % H_;
    const int tid = threadIdx.x, lane = tid & 31, wid = tid >> 5;
    const int g = lane >> 2, t4 = lane & 3;

    const __nv_bfloat16* qg = g_qh + ((size_t)bh * S_ + qt * 128) * DQK;
    const __nv_bfloat16* kg = g_kh + (size_t)bh * S_ * DQK;
    const float* vg = g_v + (size_t)(b * S_) * (H_ * DV) + h * DV;
    const int nt = 2 * qt + 2;

    // prologue: Q (8 chunks/thread) + K0 (4) + V0 (8)
    #pragma unroll
    for (int jj = 0; jj < 8; ++jj) {
        int idx = tid + jj * 256;
        int rr = idx >> 4, cc = (idx & 15) << 3;            // 8 halves = 16B
        cpa16(smb + SM_Q + (rr * QSTRH + cc) * 2, qg + (size_t)rr * DQK + cc);
    }
    #pragma unroll
    for (int jj = 0; jj < 4; ++jj) {
        int idx = tid + jj * 256;
        int rr = idx >> 4, cc = (idx & 15) << 3;
        cpa16(smb + SM_K + (rr * QSTRH + cc) * 2, kg + (size_t)rr * DQK + cc);
    }
    #pragma unroll
    for (int jj = 0; jj < 8; ++jj) {
        int idx = tid + jj * 256;
        int rr = idx >> 5, c4 = (idx & 31) << 2;            // 4 floats = 16B
        cpa16(smb + SM_V + (rr * VSTR + c4) * 4, vg + (size_t)rr * (H_*DV) + c4);
    }
    cpa_commit();

    const int r0l  = wid * 16 + g;
    const int r0gl = qt * 128 + r0l;

    float oc[16][4];
    #pragma unroll
    for (int i = 0; i < 16; ++i)
        #pragma unroll
        for (int e = 0; e < 4; ++e) oc[i][e] = 0.f;

    float m0 = -1e30f, m1 = -1e30f, l0 = 0.f, l1 = 0.f;

    for (int t = 0; t < nt; ++t) {
        cpa_wait0();
        __syncthreads();
        if (t + 1 < nt) {
            int bsel = (t + 1) & 1;
            const __nv_bfloat16* kgn = kg + (size_t)(t + 1) * 64 * DQK;
            const float* vgn = vg + (size_t)(t + 1) * 64 * (H_ * DV);
            #pragma unroll
            for (int jj = 0; jj < 4; ++jj) {
                int idx = tid + jj * 256;
                int rr = idx >> 4, cc = (idx & 15) << 3;
                cpa16(smb + SM_K + (bsel * 64 * QSTRH + rr * QSTRH + cc) * 2,
                      kgn + (size_t)rr * DQK + cc);
            }
            #pragma unroll
            for (int jj = 0; jj < 8; ++jj) {
                int idx = tid + jj * 256;
                int rr = idx >> 5, c4 = (idx & 31) << 2;
                cpa16(smb + SM_V + (bsel * 64 * VSTR + rr * VSTR + c4) * 4,
                      vgn + (size_t)rr * (H_*DV) + c4);
            }
            cpa_commit();
        }
        const unsigned* Kd32 = (const unsigned*)(smc + SM_K)
                               + (t & 1) * 64 * (QSTRH / 2);
        const float* Vd = (const float*)(smc + SM_V) + (t & 1) * 64 * VSTR;

        // ---- S = Q K^T : bf16 m16n8k16, 8 k-steps ------------------------
        float sc[8][4];
        #pragma unroll
        for (int i = 0; i < 8; ++i)
            #pragma unroll
            for (int e = 0; e < 4; ++e) sc[i][e] = 0.f;
        const unsigned* qr0 = (const unsigned*)(smc + SM_Q) + r0l * (QSTRH / 2);
        const unsigned* qr8 = qr0 + 8 * (QSTRH / 2);
        #pragma unroll
        for (int s = 0; s < 8; ++s) {
            unsigned aq[4];
            aq[0] = qr0[s * 8 + t4];
            aq[1] = qr8[s * 8 + t4];
            aq[2] = qr0[s * 8 + t4 + 4];
            aq[3] = qr8[s * 8 + t4 + 4];
            #pragma unroll
            for (int nf = 0; nf < 8; ++nf) {
                const unsigned* kr = Kd32 + (nf * 8 + g) * (QSTRH / 2);
                unsigned kb[2] = { kr[s * 8 + t4], kr[s * 8 + t4 + 4] };
                mma16bf(sc[nf], aq, kb);
            }
        }
        // ---- causal mask -------------------------------------------------
        if (t >= 2 * qt) {
            #pragma unroll
            for (int nf = 0; nf < 8; ++nf) {
                int k0 = t * 64 + nf * 8 + 2 * t4;
                if (k0     > r0gl)     sc[nf][0] = -1e30f;
                if (k0 + 1 > r0gl)     sc[nf][1] = -1e30f;
                if (k0     > r0gl + 8) sc[nf][2] = -1e30f;
                if (k0 + 1 > r0gl + 8) sc[nf][3] = -1e30f;
            }
        }
        // ---- online softmax on register fragments ------------------------
        float ml0 = -1e30f, ml1 = -1e30f;
        #pragma unroll
        for (int nf = 0; nf < 8; ++nf) {
            ml0 = fmaxf(ml0, fmaxf(sc[nf][0], sc[nf][1]));
            ml1 = fmaxf(ml1, fmaxf(sc[nf][2], sc[nf][3]));
        }
        ml0 = fmaxf(ml0, __shfl_xor_sync(0xffffffffu, ml0, 1));
        ml0 = fmaxf(ml0, __shfl_xor_sync(0xffffffffu, ml0, 2));
        ml1 = fmaxf(ml1, __shfl_xor_sync(0xffffffffu, ml1, 1));
        ml1 = fmaxf(ml1, __shfl_xor_sync(0xffffffffu, ml1, 2));
        float mn0 = fmaxf(m0, ml0), mn1 = fmaxf(m1, ml1);
        float a0 = __expf(m0 - mn0), a1 = __expf(m1 - mn1);
        float s0 = 0.f, s1 = 0.f;
        #pragma unroll
        for (int nf = 0; nf < 8; ++nf) {
            float p00 = __expf(sc[nf][0] - mn0);
            float p01 = __expf(sc[nf][1] - mn0);
            float p10 = __expf(sc[nf][2] - mn1);
            float p11 = __expf(sc[nf][3] - mn1);
            s0 += p00 + p01; s1 += p10 + p11;
            sc[nf][0] = f2tff(p00); sc[nf][1] = f2tff(p01);
            sc[nf][2] = f2tff(p10); sc[nf][3] = f2tff(p11);
        }
        s0 += __shfl_xor_sync(0xffffffffu, s0, 1);
        s0 += __shfl_xor_sync(0xffffffffu, s0, 2);
        s1 += __shfl_xor_sync(0xffffffffu, s1, 1);
        s1 += __shfl_xor_sync(0xffffffffu, s1, 2);
        l0 = l0 * a0 + s0; l1 = l1 * a1 + s1;
        m0 = mn0; m1 = mn1;
        #pragma unroll
        for (int nf = 0; nf < 16; ++nf) {
            oc[nf][0] *= a0; oc[nf][1] *= a0;
            oc[nf][2] *= a1; oc[nf][3] *= a1;
        }
        // ---- O += P V (tf32) : shfl C-frag -> A-frag, scalar V loads -----
        const int srcA = (lane & ~3) | (t4 >> 1);
        const bool odd = (t4 & 1);
        #pragma unroll
        for (int ks = 0; ks < 8; ++ks) {
            float e0A = __shfl_sync(0xffffffffu, sc[ks][0], srcA);
            float e1A = __shfl_sync(0xffffffffu, sc[ks][1], srcA);
            float e2A = __shfl_sync(0xffffffffu, sc[ks][2], srcA);
            float e3A = __shfl_sync(0xffffffffu, sc[ks][3], srcA);
            float e0B = __shfl_sync(0xffffffffu, sc[ks][0], srcA + 2);
            float e1B = __shfl_sync(0xffffffffu, sc[ks][1], srcA + 2);
            float e2B = __shfl_sync(0xffffffffu, sc[ks][2], srcA + 2);
            float e3B = __shfl_sync(0xffffffffu, sc[ks][3], srcA + 2);
            unsigned pa[4];
            pa[0] = __float_as_uint(odd ? e1A : e0A);
            pa[1] = __float_as_uint(odd ? e3A : e2A);
            pa[2] = __float_as_uint(odd ? e1B : e0B);
            pa[3] = __float_as_uint(odd ? e3B : e2B);
            #pragma unroll
            for (int nf = 0; nf < 16; ++nf) {
                unsigned vb2[2];
                const float* vr = Vd + (ks * 8 + t4) * VSTR + nf * 8 + g;
                vb2[0] = __float_as_uint(vr[0]);
                vb2[1] = __float_as_uint(vr[4 * VSTR]);
                mma8(oc[nf], pa, vb2);
            }
        }
    }
    // ---- epilogue -------------------------------------------------------
    float il0 = 1.0f / l0, il1 = 1.0f / l1;
    float* ob = g_o + ((size_t)(b * S_) + r0gl) * (H_ * DV) + h * DV;
    float* ob1 = ob + 8 * (size_t)(H_ * DV);
    #pragma unroll
    for (int nf = 0; nf < 16; ++nf) {
        int col = nf * 8 + 2 * t4;
        *(float2*)(ob  + col) = make_float2(oc[nf][0] * il0, oc[nf][1] * il0);
        *(float2*)(ob1 + col) = make_float2(oc[nf][2] * il1, oc[nf][3] * il1);
    }
}

// ---------------- launcher ---------------------------------------------------
extern "C" void kernel_launch(void* const* d_in, const int* in_sizes, int n_in,
                              void* d_out, int out_size) {
    const float* x         = (const float*)d_in[0];
    const int*   pos       = (const int*)  d_in[1];
    const float* W_dkv     = (const float*)d_in[2];
    const float* b_dkv     = (const float*)d_in[3];
    const float* W_dq      = (const float*)d_in[4];
    const float* b_dq      = (const float*)d_in[5];
    const float* W_uk_nope = (const float*)d_in[6];
    const float* b_uk_nope = (const float*)d_in[7];
    const float* W_uv      = (const float*)d_in[8];
    const float* b_uv      = (const float*)d_in[9];
    const float* W_uq_nope = (const float*)d_in[10];
    const float* b_uq_nope = (const float*)d_in[11];
    const float* W_uq_rope = (const float*)d_in[12];
    const float* b_uq_rope = (const float*)d_in[13];
    const float* W_uk_rope = (const float*)d_in[14];
    const float* b_uk_rope = (const float*)d_in[15];
    const float* W_o       = (const float*)d_in[16];
    const float* b_o       = (const float*)d_in[17];
    float* out = (float*)d_out;

    float *Ckv, *Cq, *qn, *qr, *kn, *kr, *v, *o;
    cudaGetSymbolAddress((void**)&Ckv, g_Ckv);
    cudaGetSymbolAddress((void**)&Cq,  g_Cq);
    cudaGetSymbolAddress((void**)&qn,  g_qnope);
    cudaGetSymbolAddress((void**)&qr,  g_qrope);
    cudaGetSymbolAddress((void**)&kn,  g_knope);
    cudaGetSymbolAddress((void**)&kr,  g_krope);
    cudaGetSymbolAddress((void**)&v,   g_v);
    cudaGetSymbolAddress((void**)&o,   g_o);

    auto launch2 = [&](GemmJob a, GemmJob b) {
        int nmax = a.N > b.N ? a.N : b.N;
        dim3 grid(nmax / 128, MTOK / 128, 2);
        gemm_tf32_dual<<<grid, 256>>>(a, b);
    };
    auto launch1 = [&](GemmJob a) {
        dim3 grid(a.N / 128, MTOK / 128, 1);
        gemm_tf32_dual<<<grid, 256>>>(a, a);
    };

    // #1: dkv + dq (A = x)
    launch2({x, W_dkv, b_dkv, Ckv, DL, DM, 0}, {x, W_dq, b_dq, Cq, DL, DM, 0});
    // #2: uk_rope (A = x)
    launch1({x, W_uk_rope, b_uk_rope, kr, H_*64, DM, 0});
    // #3: uq_nope + uq_rope (A = Cq)
    launch2({Cq, W_uq_nope, b_uq_nope, qn, H_*64, DL, 0},
            {Cq, W_uq_rope, b_uq_rope, qr, H_*64, DL, 0});
    // #4: uk_nope + uv (A = Ckv); v tf32-rounded at producer
    launch2({Ckv, W_uk_nope, b_uk_nope, kn, H_*64, DL, 0},
            {Ckv, W_uv, b_uv, v, H_*DV, DL, 1});
    // #5: pack/rope (q/k -> bf16, q pre-scaled)
    int packTotal = MTOK * 384;
    pack_qk<<<(packTotal + 255) / 256, 256>>>(pos);
    // #6: attention
    cudaFuncSetAttribute(attn_mma, cudaFuncAttributeMaxDynamicSharedMemorySize,
                         ATT_SMEM);
    attn_mma<<<dim3(S_ / 128, B_ * H_), 256, ATT_SMEM>>>();
    // #7: output projection
    launch1({o, W_o, b_o, out, DM, H_*DV, 0});
}